// round 10
// baseline (speedup 1.0000x reference)
#include <cuda_runtime.h>
#include <cuda_bf16.h>
#include <stdint.h>

#define BUCKET_SIZE 512
#define G1    296               // blocks for pass1 / rank pass
#define WPB   8                 // warps per block
#define W     (G1 * WPB)        // 2368 warp-tiles
#define MAXNBP 8192             // padded bucket-row stride (actual nbp = 7816)
#define MAXN  4194304

// Scratch (static; no allocations)
__device__ unsigned char  g_cnt8 [(size_t)W  * MAXNBP];           // 19.4MB raw per-warp counts
__device__ unsigned short g_bsum [(size_t)G1 * MAXNBP];           //  4.85MB per-block totals
__device__ unsigned short g_bbase[(size_t)G1 * MAXNBP];           //  4.85MB clamped block bases
__device__ unsigned short g_bkt  [MAXN];                          //  8MB per-point bucket
__device__ unsigned       g_cnt  [MAXNBP];                        // per-bucket totals
__device__ unsigned       g_inv  [(size_t)MAXNBP * BUCKET_SIZE];  // 16MB slot -> point idx

// ---- Pass 1: hash + warp-private u8 counting; flush raw rows + block sums ----
__global__ __launch_bounds__(256) void psh_pass1(
    const float* __restrict__ coords, const int* __restrict__ seps,
    const int* __restrict__ hop_p, int n, int nB, int nb, int nbp, int wtile,
    unsigned long long magic_nb, float* __restrict__ out_bucket)
{
    extern __shared__ unsigned char cnt[];   // [WPB][nbp]
    const int lane = threadIdx.x & 31;
    const int wid  = threadIdx.x >> 5;
    const int nq   = nbp >> 2;
    for (int j = threadIdx.x; j < WPB * nq; j += 256)
        ((unsigned*)cnt)[j] = 0u;
    __syncthreads();
    unsigned char* cw = cnt + wid * nbp;

    const unsigned hop = (unsigned)hop_p[0];
    const int wt  = blockIdx.x * WPB + wid;
    const int beg = wt * wtile;
    const int end = min(n, beg + wtile);

    int klo = 0, khi = 0;
    if (beg < end) {
        for (int k = 0; k < nB; k++) {
            int s = __ldg(&seps[k]);
            klo += (s <= beg);
            khi += (s <= end - 1);
        }
    }

    int i = beg + lane;
    bool v = (i < end);
    float x = 0.f, y = 0.f, z = 0.f;
    if (v) { x = coords[3*i]; y = coords[3*i+1]; z = coords[3*i+2]; }

    for (int c = beg; c < end; c += 32) {
        int ni = i + 32;                        // prefetch next chunk
        bool vn = (ni < end);
        float nx = 0.f, ny = 0.f, nz = 0.f;
        if (vn) { nx = coords[3*ni]; ny = coords[3*ni+1]; nz = coords[3*ni+2]; }

        unsigned vm = __ballot_sync(0xffffffffu, v);
        if (v) {
            unsigned bid = (unsigned)klo;
            for (int k = klo; k < khi; k++) bid += (__ldg(&seps[k]) <= i);
            unsigned vx = (unsigned)(int)floorf(x);
            unsigned vy = (unsigned)(int)floorf(y);
            unsigned vz = (unsigned)(int)floorf(z);
            unsigned h = vx * 73856093u ^ vy * 19349663u ^ vz * 83492791u
                       ^ bid * 2654435761u;
            h += hop;
            unsigned q = (unsigned)__umul64hi((unsigned long long)h, magic_nb);
            unsigned b = h - q * (unsigned)nb;
            out_bucket[i] = (float)b;
            g_bkt[i] = (unsigned short)b;
            unsigned mask = __match_any_sync(vm, b);
            if (lane == __ffs(mask) - 1)
                cw[b] = (unsigned char)(cw[b] + __popc(mask));
        }
        i = ni; v = vn; x = nx; y = ny; z = nz;
    }

    // per-warp raw u8 row flush (coalesced u32, own data: no barrier needed)
    __syncwarp();
    {
        const unsigned* src = (const unsigned*)(cnt + wid * nbp);
        unsigned* dst = (unsigned*)(g_cnt8 + (size_t)wt * nbp);
        for (int j = lane; j < nq; j += 32) dst[j] = src[j];
    }

    // block sums (byte-wise SIMD over 8 warp rows; sums < 256 -> no carries)
    __syncthreads();
    unsigned short* bs = g_bsum + (size_t)blockIdx.x * nbp;
    for (int q = threadIdx.x; q < nq; q += 256) {
        unsigned s = 0;
        #pragma unroll
        for (int w = 0; w < WPB; w++)
            s += ((const unsigned*)cnt)[w * nq + q];
        uint2 pk;
        pk.x = (s & 255u) | (((s >> 8) & 255u) << 16);
        pk.y = ((s >> 16) & 255u) | ((s >> 24) << 16);
        *(uint2*)(bs + q * 4) = pk;
    }
}

// ---- Pass 2: coalesced scan over 296 block rows -> clamped u16 bases; counts ----
__global__ __launch_bounds__(256) void psh_pass2(
    int nb, int nbp, float* __restrict__ out_counts)
{
    int j = blockIdx.x * 256 + threadIdx.x;
    if (j >= nbp) return;
    unsigned carry = 0;
    #pragma unroll 8
    for (int blk = 0; blk < G1; blk++) {
        size_t o = (size_t)blk * nbp + j;
        unsigned v = (unsigned)g_bsum[o];
        g_bbase[o] = (unsigned short)min(carry, 1024u);  // >=512 -> dropped anyway
        carry += v;
    }
    if (j < nb) {
        g_cnt[j] = carry;
        out_counts[j] = (float)carry;
    }
}

// ---- Rank pass: smem counters seeded with cross-warp prefix; emit inv ----
__global__ __launch_bounds__(256) void psh_rank(int n, int nbp, int wtile)
{
    extern __shared__ unsigned char cnt[];   // [WPB][nbp], running within-block rank
    const int lane = threadIdx.x & 31;
    const int wid  = threadIdx.x >> 5;
    const int nq   = nbp >> 2;
    const int wt0  = blockIdx.x * WPB;

    // seed: exclusive prefix across this block's 8 raw warp-count rows
    for (int q = threadIdx.x; q < nq; q += 256) {
        unsigned run = 0;                     // byte-wise, sums < 256
        #pragma unroll
        for (int w = 0; w < WPB; w++) {
            unsigned v = ((const unsigned*)(g_cnt8 + (size_t)(wt0 + w) * nbp))[q];
            ((unsigned*)cnt)[w * nq + q] = run;
            run += v;
        }
    }
    __syncthreads();
    unsigned char* cw = cnt + wid * nbp;

    const int wt  = wt0 + wid;
    const int beg = wt * wtile;
    const int end = min(n, beg + wtile);
    const unsigned short* bb = g_bbase + (size_t)blockIdx.x * nbp;

    int i = beg + lane;
    bool v = (i < end);
    unsigned b    = v ? (unsigned)g_bkt[i] : 0u;
    unsigned base = v ? (unsigned)__ldg(&bb[b]) : 0u;

    for (int c = beg; c < end; c += 32) {
        int ni = i + 32;                      // prefetch next chunk
        bool vn = (ni < end);
        unsigned bn    = vn ? (unsigned)g_bkt[ni] : 0u;
        unsigned basen = vn ? (unsigned)__ldg(&bb[bn]) : 0u;

        unsigned vm = __ballot_sync(0xffffffffu, v);
        if (v) {
            unsigned mask = __match_any_sync(vm, b);
            int leader = __ffs(mask) - 1;
            unsigned local = 0;
            if (lane == leader) {
                local = cw[b];
                cw[b] = (unsigned char)(local + __popc(mask));
            }
            local = __shfl_sync(mask, local, leader);
            unsigned rank = base + local + __popc(mask & ((1u << lane) - 1u));
            if (rank < BUCKET_SIZE)
                g_inv[(size_t)b * BUCKET_SIZE + rank] = (unsigned)i;
        }
        i = ni; v = vn; b = bn; base = basen;
    }
}

// ---- Pass 4: gather, ILP=4 (independent inv->coords chains, coalesced writes) ----
__global__ __launch_bounds__(256) void psh_pass4(
    const float* __restrict__ coords, int pad_to,
    float* __restrict__ out_coord)
{
    const int base = blockIdx.x * 1024 + threadIdx.x;
    unsigned idx[4];
    bool val[4];
    #pragma unroll
    for (int k = 0; k < 4; k++) {
        int s = base + k * 256;
        val[k] = (s < pad_to) && (unsigned)(s & (BUCKET_SIZE - 1)) < g_cnt[s >> 9];
        idx[k] = val[k] ? g_inv[s] : 0u;
    }
    float xs[4], ys[4], zs[4];
    #pragma unroll
    for (int k = 0; k < 4; k++) {
        xs[k] = val[k] ? __ldg(&coords[3 * idx[k]    ]) : 0.f;
        ys[k] = val[k] ? __ldg(&coords[3 * idx[k] + 1]) : 0.f;
        zs[k] = val[k] ? __ldg(&coords[3 * idx[k] + 2]) : 0.f;
    }
    #pragma unroll
    for (int k = 0; k < 4; k++) {
        int s = base + k * 256;
        if (s < pad_to) {
            out_coord[(size_t)s * 3 + 0] = xs[k];
            out_coord[(size_t)s * 3 + 1] = ys[k];
            out_coord[(size_t)s * 3 + 2] = zs[k];
        }
    }
}

extern "C" void kernel_launch(void* const* d_in, const int* in_sizes, int n_in,
                              void* d_out, int out_size)
{
    const float* coords = (const float*)d_in[0];
    const int*   seps   = (const int*)d_in[1];
    const int*   hop_p  = (const int*)d_in[2];

    const int n  = in_sizes[0] / 3;
    const int nB = in_sizes[1];
    const int pad_to = ((n + BUCKET_SIZE - 1) / BUCKET_SIZE) * BUCKET_SIZE;
    const int nb  = pad_to / BUCKET_SIZE;
    const int nbp = (nb + 7) & ~7;           // padded row stride (mult of 8)
    const int wtile = (n + W - 1) / W;       // 1690 for n=4M

    float* out_coord  = (float*)d_out;
    float* out_counts = out_coord + (size_t)pad_to * 3;
    float* out_bucket = out_counts + nb;

    unsigned long long magic_nb = (~0ULL) / (unsigned)nb + 1ULL;

    size_t shw = (size_t)WPB * nbp;          // 62.5 KB -> 3 blocks/SM

    static bool attr_set = false;
    if (!attr_set) {
        cudaFuncSetAttribute(psh_pass1,
                             cudaFuncAttributeMaxDynamicSharedMemorySize,
                             WPB * MAXNBP);
        cudaFuncSetAttribute(psh_rank,
                             cudaFuncAttributeMaxDynamicSharedMemorySize,
                             WPB * MAXNBP);
        attr_set = true;
    }

    psh_pass1<<<G1, 256, shw>>>(coords, seps, hop_p, n, nB, nb, nbp, wtile,
                                magic_nb, out_bucket);
    psh_pass2<<<(nbp + 255) / 256, 256>>>(nb, nbp, out_counts);
    psh_rank<<<G1, 256, shw>>>(n, nbp, wtile);
    psh_pass4<<<(pad_to + 1023) / 1024, 256>>>(coords, pad_to, out_coord);
}

// round 11
// speedup vs baseline: 1.4886x; 1.4886x over previous
#include <cuda_runtime.h>
#include <cuda_bf16.h>
#include <stdint.h>

#define BUCKET_SIZE 512
#define G1    296               // blocks for pass1 / rank pass
#define WPB   8                 // warps per block
#define W     (G1 * WPB)        // 2368 warp-tiles
#define RG    64                // row-groups for hierarchical scan
#define RPG   ((W + RG - 1) / RG)   // 37
#define MAXNBP 8192             // padded bucket-row stride (actual nbp = 7824)
#define MAXN  4194304

// Scratch (static; no allocations)
__device__ unsigned char  g_cnt8  [(size_t)W * MAXNBP];          // 19.4MB per-warp-tile counts
__device__ unsigned short g_base16[(size_t)W * MAXNBP];          // 38.8MB clamped absolute bases
__device__ unsigned       g_part  [(size_t)RG * MAXNBP];         //  2MB scan partials
__device__ unsigned short g_bkt   [MAXN];                        //  8MB per-point bucket
__device__ unsigned       g_cnt   [MAXNBP];                      // per-bucket totals
__device__ unsigned       g_inv   [(size_t)MAXNBP * BUCKET_SIZE];// 16MB slot -> point idx

// ---- Pass 1: hash + warp-private u8 counting (24 warps/SM, no block barriers in loop) ----
__global__ __launch_bounds__(256) void psh_pass1(
    const float* __restrict__ coords, const int* __restrict__ seps,
    const int* __restrict__ hop_p, int n, int nB, int nb, int nbp, int wtile,
    unsigned long long magic_nb, float* __restrict__ out_bucket)
{
    extern __shared__ unsigned char cnt[];   // [WPB][nbp]
    const int lane = threadIdx.x & 31;
    const int wid  = threadIdx.x >> 5;
    for (int j = threadIdx.x; j < (WPB * nbp) >> 2; j += 256)
        ((unsigned*)cnt)[j] = 0u;
    __syncthreads();
    unsigned char* cw = cnt + wid * nbp;

    const unsigned hop = (unsigned)hop_p[0];
    const int wt  = blockIdx.x * WPB + wid;
    const int beg = wt * wtile;
    const int end = min(n, beg + wtile);

    int klo = 0, khi = 0;
    if (beg < end) {
        for (int k = 0; k < nB; k++) {
            int s = __ldg(&seps[k]);
            klo += (s <= beg);
            khi += (s <= end - 1);
        }
    }

    int i = beg + lane;
    bool v = (i < end);
    float x = 0.f, y = 0.f, z = 0.f;
    if (v) { x = coords[3*i]; y = coords[3*i+1]; z = coords[3*i+2]; }

    for (int c = beg; c < end; c += 32) {
        int ni = i + 32;                       // prefetch next chunk
        bool vn = (ni < end);
        float nx = 0.f, ny = 0.f, nz = 0.f;
        if (vn) { nx = coords[3*ni]; ny = coords[3*ni+1]; nz = coords[3*ni+2]; }

        unsigned vm = __ballot_sync(0xffffffffu, v);
        if (v) {
            unsigned bid = (unsigned)klo;
            for (int k = klo; k < khi; k++) bid += (__ldg(&seps[k]) <= i);
            unsigned vx = (unsigned)(int)floorf(x);
            unsigned vy = (unsigned)(int)floorf(y);
            unsigned vz = (unsigned)(int)floorf(z);
            unsigned h = vx * 73856093u ^ vy * 19349663u ^ vz * 83492791u
                       ^ bid * 2654435761u;
            h += hop;
            unsigned q = (unsigned)__umul64hi((unsigned long long)h, magic_nb);
            unsigned b = h - q * (unsigned)nb;
            out_bucket[i] = (float)b;
            g_bkt[i] = (unsigned short)b;
            unsigned mask = __match_any_sync(vm, b);
            if (lane == __ffs(mask) - 1)
                cw[b] = (unsigned char)(cw[b] + __popc(mask));
        }
        i = ni; v = vn; x = nx; y = ny; z = nz;
    }

    // each warp flushes its own row (u32-coalesced); no barrier needed
    __syncwarp();
    const unsigned* src = (const unsigned*)(cnt + wid * nbp);
    unsigned* dst = (unsigned*)(g_cnt8 + (size_t)wt * nbp);
    for (int j = lane; j < (nbp >> 2); j += 32) dst[j] = src[j];
}

// ---- Scan 2a: partial sums per row-group, ILP=16 buckets/thread (uint4 loads) ----
__global__ __launch_bounds__(256) void psh_pass2a(int nbp)
{
    const int nq4 = nbp >> 4;                  // uint4 groups (16 buckets each)
    int q4 = blockIdx.x * 256 + threadIdx.x;
    int rg = blockIdx.y;
    if (q4 >= nq4) return;
    int r0 = rg * RPG, r1 = min(W, r0 + RPG);
    unsigned s[16];
    #pragma unroll
    for (int t = 0; t < 16; t++) s[t] = 0;
    const uint4* rows = (const uint4*)g_cnt8;
    #pragma unroll 4
    for (int r = r0; r < r1; r++) {
        uint4 vv = rows[(size_t)r * nq4 + q4];
        unsigned wv[4] = {vv.x, vv.y, vv.z, vv.w};
        #pragma unroll
        for (int u = 0; u < 4; u++) {
            s[u*4+0] += wv[u] & 255u;
            s[u*4+1] += (wv[u] >> 8) & 255u;
            s[u*4+2] += (wv[u] >> 16) & 255u;
            s[u*4+3] += wv[u] >> 24;
        }
    }
    size_t o = (size_t)rg * nbp + q4 * 16;
    #pragma unroll
    for (int t = 0; t < 16; t++) g_part[o + t] = s[t];
}

// ---- Scan 2b: scan the RG partials per bucket; emit counts ----
__global__ __launch_bounds__(256) void psh_pass2b(
    int nb, int nbp, float* __restrict__ out_counts)
{
    int j = blockIdx.x * 256 + threadIdx.x;
    if (j >= nbp) return;
    unsigned carry = 0;
    #pragma unroll
    for (int rg = 0; rg < RG; rg++) {
        size_t o = (size_t)rg * nbp + j;
        unsigned v = g_part[o];
        g_part[o] = carry;
        carry += v;
    }
    if (j < nb) {
        g_cnt[j] = carry;
        out_counts[j] = (float)carry;
    }
}

// ---- Scan 2c: rescan rows -> clamped u16 absolute bases, ILP=16 buckets/thread ----
__global__ __launch_bounds__(256) void psh_pass2c(int nbp)
{
    const int nq4 = nbp >> 4;
    int q4 = blockIdx.x * 256 + threadIdx.x;
    int rg = blockIdx.y;
    if (q4 >= nq4) return;
    int r0 = rg * RPG, r1 = min(W, r0 + RPG);
    size_t o = (size_t)rg * nbp + q4 * 16;
    unsigned a[16];
    #pragma unroll
    for (int t = 0; t < 16; t++) a[t] = g_part[o + t];
    const uint4* rows = (const uint4*)g_cnt8;
    #pragma unroll 2
    for (int r = r0; r < r1; r++) {
        uint4 p0, p1;
        p0.x = min(a[0],1024u)  | (min(a[1],1024u)  << 16);
        p0.y = min(a[2],1024u)  | (min(a[3],1024u)  << 16);
        p0.z = min(a[4],1024u)  | (min(a[5],1024u)  << 16);
        p0.w = min(a[6],1024u)  | (min(a[7],1024u)  << 16);
        p1.x = min(a[8],1024u)  | (min(a[9],1024u)  << 16);
        p1.y = min(a[10],1024u) | (min(a[11],1024u) << 16);
        p1.z = min(a[12],1024u) | (min(a[13],1024u) << 16);
        p1.w = min(a[14],1024u) | (min(a[15],1024u) << 16);
        uint4* bout = (uint4*)(g_base16 + (size_t)r * nbp + q4 * 16);
        bout[0] = p0;
        bout[1] = p1;
        uint4 vv = rows[(size_t)r * nq4 + q4];
        unsigned wv[4] = {vv.x, vv.y, vv.z, vv.w};
        #pragma unroll
        for (int u = 0; u < 4; u++) {
            a[u*4+0] += wv[u] & 255u;
            a[u*4+1] += (wv[u] >> 8) & 255u;
            a[u*4+2] += (wv[u] >> 16) & 255u;
            a[u*4+3] += wv[u] >> 24;
        }
    }
}

// ---- Rank pass: warp-private u8 counters + prefetched base; emit inv (4B, L2-hot) ----
__global__ __launch_bounds__(256) void psh_rank(int n, int nbp, int wtile)
{
    extern __shared__ unsigned char cnt[];   // [WPB][nbp]
    const int lane = threadIdx.x & 31;
    const int wid  = threadIdx.x >> 5;
    for (int j = threadIdx.x; j < (WPB * nbp) >> 2; j += 256)
        ((unsigned*)cnt)[j] = 0u;
    __syncthreads();
    unsigned char* cw = cnt + wid * nbp;

    const int wt  = blockIdx.x * WPB + wid;
    const int beg = wt * wtile;
    const int end = min(n, beg + wtile);
    const unsigned short* baserow = g_base16 + (size_t)wt * nbp;

    int i = beg + lane;
    bool v = (i < end);
    unsigned b    = v ? (unsigned)g_bkt[i] : 0u;
    unsigned base = v ? (unsigned)__ldg(&baserow[b]) : 0u;

    for (int c = beg; c < end; c += 32) {
        int ni = i + 32;                      // prefetch next chunk (bkt + base)
        bool vn = (ni < end);
        unsigned bn    = vn ? (unsigned)g_bkt[ni] : 0u;
        unsigned basen = vn ? (unsigned)__ldg(&baserow[bn]) : 0u;

        unsigned vm = __ballot_sync(0xffffffffu, v);
        if (v) {
            unsigned mask = __match_any_sync(vm, b);
            int leader = __ffs(mask) - 1;
            unsigned local = 0;
            if (lane == leader) {
                local = cw[b];
                cw[b] = (unsigned char)(local + __popc(mask));
            }
            local = __shfl_sync(mask, local, leader);
            unsigned rank = base + local + __popc(mask & ((1u << lane) - 1u));
            if (rank < BUCKET_SIZE)
                g_inv[(size_t)b * BUCKET_SIZE + rank] = (unsigned)i;
        }
        i = ni; v = vn; b = bn; base = basen;
    }
}

// ---- Pass 4: gather — coalesced full-sector output writes (R8-proven shape) ----
__global__ __launch_bounds__(256) void psh_pass4(
    const float* __restrict__ coords, int pad_to,
    float* __restrict__ out_coord)
{
    int s = blockIdx.x * 256 + threadIdx.x;
    if (s >= pad_to) return;
    int b = s >> 9;
    int r = s & (BUCKET_SIZE - 1);
    float x = 0.f, y = 0.f, z = 0.f;
    if ((unsigned)r < g_cnt[b]) {
        unsigned i = g_inv[s];
        x = __ldg(&coords[3*i]);
        y = __ldg(&coords[3*i+1]);
        z = __ldg(&coords[3*i+2]);
    }
    out_coord[(size_t)s * 3 + 0] = x;
    out_coord[(size_t)s * 3 + 1] = y;
    out_coord[(size_t)s * 3 + 2] = z;
}

extern "C" void kernel_launch(void* const* d_in, const int* in_sizes, int n_in,
                              void* d_out, int out_size)
{
    const float* coords = (const float*)d_in[0];
    const int*   seps   = (const int*)d_in[1];
    const int*   hop_p  = (const int*)d_in[2];

    const int n  = in_sizes[0] / 3;
    const int nB = in_sizes[1];
    const int pad_to = ((n + BUCKET_SIZE - 1) / BUCKET_SIZE) * BUCKET_SIZE;
    const int nb  = pad_to / BUCKET_SIZE;
    const int nbp = (nb + 15) & ~15;         // padded row stride (mult of 16)
    const int wtile = (n + W - 1) / W;       // 1690 for n=4M

    float* out_coord  = (float*)d_out;
    float* out_counts = out_coord + (size_t)pad_to * 3;
    float* out_bucket = out_counts + nb;

    unsigned long long magic_nb = (~0ULL) / (unsigned)nb + 1ULL;

    size_t shw = (size_t)WPB * nbp;          // ~62.6 KB -> 3 blocks/SM

    static bool attr_set = false;
    if (!attr_set) {
        cudaFuncSetAttribute(psh_pass1,
                             cudaFuncAttributeMaxDynamicSharedMemorySize,
                             WPB * MAXNBP);
        cudaFuncSetAttribute(psh_rank,
                             cudaFuncAttributeMaxDynamicSharedMemorySize,
                             WPB * MAXNBP);
        attr_set = true;
    }

    const int nq4 = nbp >> 4;
    dim3 gscan((nq4 + 255) / 256, RG);
    psh_pass1<<<G1, 256, shw>>>(coords, seps, hop_p, n, nB, nb, nbp, wtile,
                                magic_nb, out_bucket);
    psh_pass2a<<<gscan, 256>>>(nbp);
    psh_pass2b<<<(nbp + 255) / 256, 256>>>(nb, nbp, out_counts);
    psh_pass2c<<<gscan, 256>>>(nbp);
    psh_rank<<<G1, 256, shw>>>(n, nbp, wtile);
    psh_pass4<<<(pad_to + 255) / 256, 256>>>(coords, pad_to, out_coord);
}

// round 12
// speedup vs baseline: 1.5444x; 1.0374x over previous
#include <cuda_runtime.h>
#include <cuda_bf16.h>
#include <stdint.h>

#define BUCKET_SIZE 512
#define G1    296               // blocks for pass1 / rank pass
#define WPB   8                 // warps per block
#define W     (G1 * WPB)        // 2368 warp-tiles
#define RG    64                // row-groups for hierarchical scan
#define RPG   ((W + RG - 1) / RG)   // 37
#define MAXNBP 8192             // padded bucket-row stride (actual nbp = 7824)
#define MAXN  4194304

// Scratch (static; no allocations)
__device__ unsigned char  g_cnt8  [(size_t)W * MAXNBP];          // 19.4MB per-warp-tile counts
__device__ unsigned short g_base16[(size_t)W * MAXNBP];          // 38.8MB clamped absolute bases
__device__ unsigned       g_part  [(size_t)RG * MAXNBP];         //  2MB scan partials
__device__ unsigned short g_bkt   [MAXN];                        //  8MB per-point bucket
__device__ unsigned       g_cnt   [MAXNBP];                      // per-bucket totals
__device__ unsigned       g_inv   [(size_t)MAXNBP * BUCKET_SIZE];// 16MB slot -> point idx

// ---- Pass 1: hash + warp-private u8 counting (24 warps/SM, no block barriers in loop) ----
__global__ __launch_bounds__(256) void psh_pass1(
    const float* __restrict__ coords, const int* __restrict__ seps,
    const int* __restrict__ hop_p, int n, int nB, int nb, int nbp, int wtile,
    unsigned long long magic_nb, float* __restrict__ out_bucket)
{
    extern __shared__ unsigned char cnt[];   // [WPB][nbp]
    const int lane = threadIdx.x & 31;
    const int wid  = threadIdx.x >> 5;
    for (int j = threadIdx.x; j < (WPB * nbp) >> 2; j += 256)
        ((unsigned*)cnt)[j] = 0u;
    __syncthreads();
    unsigned char* cw = cnt + wid * nbp;

    const unsigned hop = (unsigned)hop_p[0];
    const int wt  = blockIdx.x * WPB + wid;
    const int beg = wt * wtile;
    const int end = min(n, beg + wtile);

    int klo = 0, khi = 0;
    if (beg < end) {
        for (int k = 0; k < nB; k++) {
            int s = __ldg(&seps[k]);
            klo += (s <= beg);
            khi += (s <= end - 1);
        }
    }

    int i = beg + lane;
    bool v = (i < end);
    float x = 0.f, y = 0.f, z = 0.f;
    if (v) { x = coords[3*i]; y = coords[3*i+1]; z = coords[3*i+2]; }

    for (int c = beg; c < end; c += 32) {
        int ni = i + 32;                       // prefetch next chunk
        bool vn = (ni < end);
        float nx = 0.f, ny = 0.f, nz = 0.f;
        if (vn) { nx = coords[3*ni]; ny = coords[3*ni+1]; nz = coords[3*ni+2]; }

        unsigned vm = __ballot_sync(0xffffffffu, v);
        if (v) {
            unsigned bid = (unsigned)klo;
            for (int k = klo; k < khi; k++) bid += (__ldg(&seps[k]) <= i);
            unsigned vx = (unsigned)(int)floorf(x);
            unsigned vy = (unsigned)(int)floorf(y);
            unsigned vz = (unsigned)(int)floorf(z);
            unsigned h = vx * 73856093u ^ vy * 19349663u ^ vz * 83492791u
                       ^ bid * 2654435761u;
            h += hop;
            unsigned q = (unsigned)__umul64hi((unsigned long long)h, magic_nb);
            unsigned b = h - q * (unsigned)nb;
            out_bucket[i] = (float)b;
            g_bkt[i] = (unsigned short)b;
            unsigned mask = __match_any_sync(vm, b);
            if (lane == __ffs(mask) - 1)
                cw[b] = (unsigned char)(cw[b] + __popc(mask));
        }
        i = ni; v = vn; x = nx; y = ny; z = nz;
    }

    // each warp flushes its own row (u32-coalesced); no barrier needed
    __syncwarp();
    const unsigned* src = (const unsigned*)(cnt + wid * nbp);
    unsigned* dst = (unsigned*)(g_cnt8 + (size_t)wt * nbp);
    for (int j = lane; j < (nbp >> 2); j += 32) dst[j] = src[j];
}

// ---- Scan 2a: partial sums per row-group, ILP=4 buckets/thread, 512 blocks ----
__global__ __launch_bounds__(256) void psh_pass2a(int nbp)
{
    const int nq = nbp >> 2;                   // u32 groups (4 buckets each)
    int q  = blockIdx.x * 256 + threadIdx.x;
    int rg = blockIdx.y;
    if (q >= nq) return;
    int r0 = rg * RPG, r1 = min(W, r0 + RPG);
    unsigned s0 = 0, s1 = 0, s2 = 0, s3 = 0;
    const unsigned* rows = (const unsigned*)g_cnt8;
    #pragma unroll 4
    for (int r = r0; r < r1; r++) {
        unsigned vv = rows[(size_t)r * nq + q];
        s0 += vv & 255u;         s1 += (vv >> 8) & 255u;
        s2 += (vv >> 16) & 255u; s3 += vv >> 24;
    }
    size_t o = (size_t)rg * nbp + q * 4;
    g_part[o] = s0; g_part[o+1] = s1; g_part[o+2] = s2; g_part[o+3] = s3;
}

// ---- Scan 2b: scan the RG partials per bucket; emit counts ----
__global__ __launch_bounds__(256) void psh_pass2b(
    int nb, int nbp, float* __restrict__ out_counts)
{
    int j = blockIdx.x * 256 + threadIdx.x;
    if (j >= nbp) return;
    unsigned carry = 0;
    #pragma unroll
    for (int rg = 0; rg < RG; rg++) {
        size_t o = (size_t)rg * nbp + j;
        unsigned v = g_part[o];
        g_part[o] = carry;
        carry += v;
    }
    if (j < nb) {
        g_cnt[j] = carry;
        out_counts[j] = (float)carry;
    }
}

// ---- Scan 2c: rescan rows -> clamped u16 bases, ILP=4 buckets/thread, 512 blocks ----
__global__ __launch_bounds__(256) void psh_pass2c(int nbp)
{
    const int nq = nbp >> 2;
    int q  = blockIdx.x * 256 + threadIdx.x;
    int rg = blockIdx.y;
    if (q >= nq) return;
    int r0 = rg * RPG, r1 = min(W, r0 + RPG);
    size_t o = (size_t)rg * nbp + q * 4;
    unsigned a0 = g_part[o], a1 = g_part[o+1], a2 = g_part[o+2], a3 = g_part[o+3];
    const unsigned* rows = (const unsigned*)g_cnt8;
    #pragma unroll 4
    for (int r = r0; r < r1; r++) {
        uint2 pk;
        pk.x = min(a0, 1024u) | (min(a1, 1024u) << 16);
        pk.y = min(a2, 1024u) | (min(a3, 1024u) << 16);
        *(uint2*)(g_base16 + (size_t)r * nbp + q * 4) = pk;
        unsigned vv = rows[(size_t)r * nq + q];
        a0 += vv & 255u;         a1 += (vv >> 8) & 255u;
        a2 += (vv >> 16) & 255u; a3 += vv >> 24;
    }
}

// ---- Rank pass: warp-private u8 counters + prefetched base; emit inv (4B, L2-hot) ----
__global__ __launch_bounds__(256) void psh_rank(int n, int nbp, int wtile)
{
    extern __shared__ unsigned char cnt[];   // [WPB][nbp]
    const int lane = threadIdx.x & 31;
    const int wid  = threadIdx.x >> 5;
    for (int j = threadIdx.x; j < (WPB * nbp) >> 2; j += 256)
        ((unsigned*)cnt)[j] = 0u;
    __syncthreads();
    unsigned char* cw = cnt + wid * nbp;

    const int wt  = blockIdx.x * WPB + wid;
    const int beg = wt * wtile;
    const int end = min(n, beg + wtile);
    const unsigned short* baserow = g_base16 + (size_t)wt * nbp;

    int i = beg + lane;
    bool v = (i < end);
    unsigned b    = v ? (unsigned)g_bkt[i] : 0u;
    unsigned base = v ? (unsigned)__ldg(&baserow[b]) : 0u;

    for (int c = beg; c < end; c += 32) {
        int ni = i + 32;                      // prefetch next chunk (bkt + base)
        bool vn = (ni < end);
        unsigned bn    = vn ? (unsigned)g_bkt[ni] : 0u;
        unsigned basen = vn ? (unsigned)__ldg(&baserow[bn]) : 0u;

        unsigned vm = __ballot_sync(0xffffffffu, v);
        if (v) {
            unsigned mask = __match_any_sync(vm, b);
            int leader = __ffs(mask) - 1;
            unsigned local = 0;
            if (lane == leader) {
                local = cw[b];
                cw[b] = (unsigned char)(local + __popc(mask));
            }
            local = __shfl_sync(mask, local, leader);
            unsigned rank = base + local + __popc(mask & ((1u << lane) - 1u));
            if (rank < BUCKET_SIZE)
                g_inv[(size_t)b * BUCKET_SIZE + rank] = (unsigned)i;
        }
        i = ni; v = vn; b = bn; base = basen;
    }
}

// ---- Pass 4: gather — coalesced full-sector output writes (proven shape) ----
__global__ __launch_bounds__(256) void psh_pass4(
    const float* __restrict__ coords, int pad_to,
    float* __restrict__ out_coord)
{
    int s = blockIdx.x * 256 + threadIdx.x;
    if (s >= pad_to) return;
    int b = s >> 9;
    int r = s & (BUCKET_SIZE - 1);
    float x = 0.f, y = 0.f, z = 0.f;
    if ((unsigned)r < g_cnt[b]) {
        unsigned i = g_inv[s];
        x = __ldg(&coords[3*i]);
        y = __ldg(&coords[3*i+1]);
        z = __ldg(&coords[3*i+2]);
    }
    out_coord[(size_t)s * 3 + 0] = x;
    out_coord[(size_t)s * 3 + 1] = y;
    out_coord[(size_t)s * 3 + 2] = z;
}

extern "C" void kernel_launch(void* const* d_in, const int* in_sizes, int n_in,
                              void* d_out, int out_size)
{
    const float* coords = (const float*)d_in[0];
    const int*   seps   = (const int*)d_in[1];
    const int*   hop_p  = (const int*)d_in[2];

    const int n  = in_sizes[0] / 3;
    const int nB = in_sizes[1];
    const int pad_to = ((n + BUCKET_SIZE - 1) / BUCKET_SIZE) * BUCKET_SIZE;
    const int nb  = pad_to / BUCKET_SIZE;
    const int nbp = (nb + 7) & ~7;           // padded row stride (mult of 8)
    const int wtile = (n + W - 1) / W;       // 1690 for n=4M

    float* out_coord  = (float*)d_out;
    float* out_counts = out_coord + (size_t)pad_to * 3;
    float* out_bucket = out_counts + nb;

    unsigned long long magic_nb = (~0ULL) / (unsigned)nb + 1ULL;

    size_t shw = (size_t)WPB * nbp;          // ~62.5 KB -> 3 blocks/SM

    static bool attr_set = false;
    if (!attr_set) {
        cudaFuncSetAttribute(psh_pass1,
                             cudaFuncAttributeMaxDynamicSharedMemorySize,
                             WPB * MAXNBP);
        cudaFuncSetAttribute(psh_rank,
                             cudaFuncAttributeMaxDynamicSharedMemorySize,
                             WPB * MAXNBP);
        attr_set = true;
    }

    const int nq = nbp >> 2;
    dim3 gscan((nq + 255) / 256, RG);
    psh_pass1<<<G1, 256, shw>>>(coords, seps, hop_p, n, nB, nb, nbp, wtile,
                                magic_nb, out_bucket);
    psh_pass2a<<<gscan, 256>>>(nbp);
    psh_pass2b<<<(nbp + 255) / 256, 256>>>(nb, nbp, out_counts);
    psh_pass2c<<<gscan, 256>>>(nbp);
    psh_rank<<<G1, 256, shw>>>(n, nbp, wtile);
    psh_pass4<<<(pad_to + 255) / 256, 256>>>(coords, pad_to, out_coord);
}